// round 15
// baseline (speedup 1.0000x reference)
#include <cuda_runtime.h>
#include <math.h>

#define BB 16
#define CC 256
#define PP 64
#define NN 256
#define PN 16384
#define FF 512
#define CPN (CC*PN)
#define STR 68

__device__ float g_WkG1T[CC*CC], g_WkG2T[CC*CC], g_WvG1T[CC*CC], g_WvG2T[CC*CC];
__device__ float g_Wout1T[CC*CC], g_Wout2T[CC*CC];
__device__ float g_Wf1GT[CC*FF];
__device__ float g_Wf2T[FF*CC];
__device__ float g_wq1[CC], g_wq2[CC];
__device__ float g_Sk1[CC], g_tbk1[CC], g_Sk2[CC], g_tbk2[CC];
__device__ float g_Sv1[CC], g_tbv1[CC], g_Sv2[CC], g_tbv2[CC];
__device__ float g_Sf1[FF], g_tbf1[FF];
__device__ float g_z1[BB*PN], g_z2[BB*PN];
__device__ float g_xs1[BB*CC*NN], g_xs2[BB*CC*PP];
__device__ float g_ctx1[BB*CC*NN], g_ctx2[BB*CC*PP];
__device__ float g_stats[BB*4], g_stats2[BB*4];
__device__ float g_xmid[(size_t)BB*CC*PN];

__device__ __forceinline__ unsigned long long ffma2(unsigned long long a,
                                                    unsigned long long b,
                                                    unsigned long long c) {
    unsigned long long d;
    asm("fma.rn.f32x2 %0, %1, %2, %3;" : "=l"(d) : "l"(a), "l"(b), "l"(c));
    return d;
}
__device__ __forceinline__ unsigned long long bcast2(float w) {
    unsigned long long r; unsigned u = __float_as_uint(w);
    asm("mov.b64 %0, {%1, %2};" : "=l"(r) : "r"(u), "r"(u));
    return r;
}
__device__ __forceinline__ float2 unpk(unsigned long long v) {
    unsigned lo, hi;
    asm("mov.b64 {%0, %1}, %2;" : "=r"(lo), "=r"(hi) : "l"(v));
    return make_float2(__uint_as_float(lo), __uint_as_float(hi));
}

__global__ void zero_kernel() {
    int t = threadIdx.x;
    if (t < BB*4) { g_stats[t] = 0.f; g_stats2[t] = 0.f; }
}

__global__ void fold_kernel(const float* __restrict__ Wqkv1, const float* __restrict__ bqkv1,
                            const float* __restrict__ g1,    const float* __restrict__ b1,
                            const float* __restrict__ Wqkv2, const float* __restrict__ bqkv2,
                            const float* __restrict__ g2,    const float* __restrict__ b2,
                            const float* __restrict__ Wf1,   const float* __restrict__ bf1,
                            const float* __restrict__ gf,    const float* __restrict__ bf,
                            const float* __restrict__ Wout1, const float* __restrict__ Wout2,
                            const float* __restrict__ Wf2) {
    int blk = blockIdx.x, t = threadIdx.x;
    __shared__ float red[256], red2[256];
    if (blk < 1024) {
        int sec = blk >> 8, o = blk & 255;
        const float *W, *bq, *g, *b; float *WT, *S, *TB; int row;
        if (sec == 0)      { W=Wqkv1; bq=bqkv1; g=g1; b=b1; WT=g_WkG1T; S=g_Sk1; TB=g_tbk1; row=1+o; }
        else if (sec == 1) { W=Wqkv1; bq=bqkv1; g=g1; b=b1; WT=g_WvG1T; S=g_Sv1; TB=g_tbv1; row=1+CC+o; }
        else if (sec == 2) { W=Wqkv2; bq=bqkv2; g=g2; b=b2; WT=g_WkG2T; S=g_Sk2; TB=g_tbk2; row=1+o; }
        else               { W=Wqkv2; bq=bqkv2; g=g2; b=b2; WT=g_WvG2T; S=g_Sv2; TB=g_tbv2; row=1+CC+o; }
        float w  = W[row*CC + t];
        float wg = w * g[t];
        WT[t*CC + o] = wg;
        red[t] = wg; red2[t] = w * b[t];
        __syncthreads();
        for (int s = 128; s > 0; s >>= 1) {
            if (t < s) { red[t] += red[t+s]; red2[t] += red2[t+s]; }
            __syncthreads();
        }
        if (t == 0) { S[o] = red[0]; TB[o] = red2[0] + bq[row]; }
    } else if (blk < 1536) {
        int f = blk - 1024;
        float w  = Wf1[f*CC + t];
        float wg = w * gf[t];
        g_Wf1GT[t*FF + f] = wg;
        red[t] = wg; red2[t] = w * bf[t];
        __syncthreads();
        for (int s = 128; s > 0; s >>= 1) {
            if (t < s) { red[t] += red[t+s]; red2[t] += red2[t+s]; }
            __syncthreads();
        }
        if (t == 0) { g_Sf1[f] = red[0]; g_tbf1[f] = red2[0] + bf1[f]; }
    } else if (blk < 1792) {
        int o = blk - 1536; g_Wout1T[t*CC + o] = Wout1[o*CC + t];
    } else if (blk < 2048) {
        int o = blk - 1792; g_Wout2T[t*CC + o] = Wout2[o*CC + t];
    } else if (blk < 2304) {
        int o = blk - 2048;
        g_Wf2T[t*CC + o]       = Wf2[o*FF + t];
        g_Wf2T[(t+256)*CC + o] = Wf2[o*FF + t + 256];
    } else {
        g_wq1[t] = Wqkv1[t] * g1[t];
        g_wq2[t] = Wqkv2[t] * g2[t];
    }
}

__global__ void qstats_kernel(const float* __restrict__ x) {
    int b    = blockIdx.x >> 4;
    int pix0 = (blockIdx.x & 15) * 1024;
    int t    = threadIdx.x;
    __shared__ float sw1[CC], sw2[CC];
    sw1[t] = g_wq1[t]; sw2[t] = g_wq2[t];
    __syncthreads();
    const float* xb = x + (size_t)b*CPN + pix0 + t*4;
    float a1x=0,a1y=0,a1z=0,a1w=0, a2x=0,a2y=0,a2z=0,a2w=0, s=0, ss=0;
    for (int c = 0; c < CC; c++) {
        float4 v = *(const float4*)(xb + (size_t)c*PN);
        float w1 = sw1[c], w2 = sw2[c];
        a1x = fmaf(w1,v.x,a1x); a1y = fmaf(w1,v.y,a1y); a1z = fmaf(w1,v.z,a1z); a1w = fmaf(w1,v.w,a1w);
        a2x = fmaf(w2,v.x,a2x); a2y = fmaf(w2,v.y,a2y); a2z = fmaf(w2,v.z,a2z); a2w = fmaf(w2,v.w,a2w);
        s  += v.x + v.y + v.z + v.w;
        ss += v.x*v.x + v.y*v.y + v.z*v.z + v.w*v.w;
    }
    size_t o = (size_t)b*PN + pix0 + t*4;
    *(float4*)(g_z1 + o) = make_float4(a1x,a1y,a1z,a1w);
    *(float4*)(g_z2 + o) = make_float4(a2x,a2y,a2z,a2w);
    __shared__ float rs[256], rss[256];
    rs[t] = s; rss[t] = ss; __syncthreads();
    for (int st = 128; st > 0; st >>= 1) {
        if (t < st) { rs[t] += rs[t+st]; rss[t] += rss[t+st]; }
        __syncthreads();
    }
    if (t == 0) { atomicAdd(&g_stats[b*4+0], rs[0]); atomicAdd(&g_stats[b*4+1], rss[0]); }
}

__global__ void finalize_kernel(int which) {
    float* st = which ? g_stats2 : g_stats;
    int t = threadIdx.x;
    if (t < BB) {
        float mu  = st[t*4+0] * (1.0f/(float)CPN);
        float var = st[t*4+1] * (1.0f/(float)CPN) - mu*mu;
        st[t*4+2] = mu;
        st[t*4+3] = rsqrtf(var + 1e-5f);
    }
}

__global__ void softmax_n_kernel() {
    int b = blockIdx.x / PP, p = blockIdx.x % PP, t = threadIdx.x;
    float inv = g_stats[b*4+3];
    float* z = g_z2 + (size_t)b*PN + p*NN;
    __shared__ float red[256];
    float v = z[t] * inv;
    red[t] = v; __syncthreads();
    for (int s = 128; s > 0; s >>= 1) { if (t < s) red[t] = fmaxf(red[t], red[t+s]); __syncthreads(); }
    float m = red[0]; __syncthreads();
    float e = expf(v - m);
    red[t] = e; __syncthreads();
    for (int s = 128; s > 0; s >>= 1) { if (t < s) red[t] += red[t+s]; __syncthreads(); }
    z[t] = e / red[0];
}

__global__ void softmax_p_kernel() {
    int b = blockIdx.x / NN, n = blockIdx.x % NN, t = threadIdx.x;
    float inv = g_stats[b*4+3];
    float* z = g_z1 + (size_t)b*PN + n;
    __shared__ float red[64];
    float v = z[t*NN] * inv;
    red[t] = v; __syncthreads();
    for (int s = 32; s > 0; s >>= 1) { if (t < s) red[t] = fmaxf(red[t], red[t+s]); __syncthreads(); }
    float m = red[0]; __syncthreads();
    float e = expf(v - m);
    red[t] = e; __syncthreads();
    for (int s = 32; s > 0; s >>= 1) { if (t < s) red[t] += red[t+s]; __syncthreads(); }
    z[t*NN] = e / red[0];
}

__global__ void xs_kernel(const float* __restrict__ x) {
    int b = blockIdx.x >> 8, c = blockIdx.x & 255, t = threadIdx.x;
    const float* xc = x    + ((size_t)b*CC + c)*PN;
    const float* s1 = g_z1 + (size_t)b*PN;
    const float* s2 = g_z2 + (size_t)b*PN;
    __shared__ float warpsum[8];
    __shared__ float out2[PP];
    float acc1 = 0.f;
    for (int p = 0; p < PP; p++) {
        float v = xc[p*NN + t];
        acc1 = fmaf(v, s1[p*NN + t], acc1);
        float pr = v * s2[p*NN + t];
        for (int o = 16; o > 0; o >>= 1) pr += __shfl_down_sync(0xffffffffu, pr, o);
        if ((t & 31) == 0) warpsum[t >> 5] = pr;
        __syncthreads();
        if (t < 8) {
            float u = warpsum[t];
            for (int o = 4; o > 0; o >>= 1) u += __shfl_down_sync(0xffu, u, o);
            if (t == 0) out2[p] = u;
        }
        __syncthreads();
    }
    g_xs1[((size_t)b*CC + c)*NN + t] = acc1;
    if (t < PP) g_xs2[((size_t)b*CC + c)*PP + t] = out2[t];
}

__global__ void ctx_kernel() {
    extern __shared__ float Xs[];
    int b = blockIdx.x / 5, tile = blockIdx.x % 5, t = threadIdx.x;
    float mu = g_stats[b*4+2], inv = g_stats[b*4+3];
    const float *in, *WT, *S, *TB; float* out; int stride;
    if (tile < 4) {
        in  = g_xs1  + ((size_t)b*CC)*NN + tile*64;
        out = g_ctx1 + ((size_t)b*CC)*NN + tile*64;
        WT = g_WkG1T; S = g_Sk1; TB = g_tbk1; stride = NN;
    } else {
        in  = g_xs2  + ((size_t)b*CC)*PP;
        out = g_ctx2 + ((size_t)b*CC)*PP;
        WT = g_WkG2T; S = g_Sk2; TB = g_tbk2; stride = PP;
    }
    for (int i = t; i < CC*64; i += 256) {
        int c = i >> 6, j = i & 63;
        Xs[i] = in[(size_t)c*stride + j];
    }
    __syncthreads();
    float acc[64];
    #pragma unroll
    for (int j = 0; j < 64; j++) acc[j] = 0.f;
    for (int c = 0; c < CC; c++) {
        float w = WT[c*CC + t];
        const float* xr = &Xs[c*64];
        #pragma unroll
        for (int j = 0; j < 64; j++) acc[j] = fmaf(w, xr[j], acc[j]);
    }
    float d = TB[t] - inv*mu*S[t];
    for (int j = 0; j < 64; j++) out[(size_t)t*stride + j] = fmaf(inv, acc[j], d);
}

__global__ __launch_bounds__(256, 1)
void attn_kernel(const float* __restrict__ x,
                 const float* __restrict__ bout1, const float* __restrict__ bout2) {
    extern __shared__ float sm[];
    float* Xt = sm;
    float* Ot = sm + CC*STR;
    __shared__ float rs[256], rss[256];
    int blk  = blockIdx.x;
    int b    = blk >> 8;
    int pix0 = (blk & 255) * 64;
    int p    = pix0 >> 8;
    int n0   = pix0 & 255;
    int t    = threadIdx.x;
    float mu = g_stats[b*4+2], inv = g_stats[b*4+3];
    const float* xb = x + ((size_t)b*CC)*PN + pix0;
    for (int i = t; i < CC*64; i += 256) {
        int c = i >> 6, j = i & 63;
        Xt[c*STR + j] = xb[(size_t)c*PN + j];
    }
    __syncthreads();

    unsigned long long acc[32], yacc[32];
    #pragma unroll
    for (int j = 0; j < 32; j++) acc[j] = 0ULL;
    #pragma unroll 2
    for (int c = 0; c < CC; c++) {
        unsigned long long wp = bcast2(g_WvG1T[c*CC + t]);
        const ulonglong2* xr = (const ulonglong2*)&Xt[c*STR];
        #pragma unroll
        for (int q = 0; q < 16; q++) {
            ulonglong2 v = xr[q];
            acc[2*q]   = ffma2(wp, v.x, acc[2*q]);
            acc[2*q+1] = ffma2(wp, v.y, acc[2*q+1]);
        }
    }
    {
        float d = g_tbv1[t] - inv*mu*g_Sv1[t];
        const float* c1 = g_ctx1 + ((size_t)b*CC + t)*NN + n0;
        #pragma unroll
        for (int j = 0; j < 32; j++) {
            float2 a = unpk(acc[j]);
            float v0 = fmaxf(fmaf(inv, a.x, d), 0.f);
            float v1 = fmaxf(fmaf(inv, a.y, d), 0.f);
            Ot[t*STR + 2*j]   = v0 * c1[2*j];
            Ot[t*STR + 2*j+1] = v1 * c1[2*j+1];
        }
    }
    __syncthreads();
    #pragma unroll
    for (int j = 0; j < 32; j++) yacc[j] = 0ULL;
    #pragma unroll 2
    for (int c = 0; c < CC; c++) {
        unsigned long long wp = bcast2(g_Wout1T[c*CC + t]);
        const ulonglong2* orow = (const ulonglong2*)&Ot[c*STR];
        #pragma unroll
        for (int q = 0; q < 16; q++) {
            ulonglong2 v = orow[q];
            yacc[2*q]   = ffma2(wp, v.x, yacc[2*q]);
            yacc[2*q+1] = ffma2(wp, v.y, yacc[2*q+1]);
        }
    }
    __syncthreads();
    #pragma unroll
    for (int j = 0; j < 32; j++) acc[j] = 0ULL;
    #pragma unroll 2
    for (int c = 0; c < CC; c++) {
        unsigned long long wp = bcast2(g_WvG2T[c*CC + t]);
        const ulonglong2* xr = (const ulonglong2*)&Xt[c*STR];
        #pragma unroll
        for (int q = 0; q < 16; q++) {
            ulonglong2 v = xr[q];
            acc[2*q]   = ffma2(wp, v.x, acc[2*q]);
            acc[2*q+1] = ffma2(wp, v.y, acc[2*q+1]);
        }
    }
    {
        float d   = g_tbv2[t] - inv*mu*g_Sv2[t];
        float c2v = g_ctx2[((size_t)b*CC + t)*PP + p];
        #pragma unroll
        for (int j = 0; j < 32; j++) {
            float2 a = unpk(acc[j]);
            float v0 = fmaxf(fmaf(inv, a.x, d), 0.f);
            float v1 = fmaxf(fmaf(inv, a.y, d), 0.f);
            Ot[t*STR + 2*j]   = v0 * c2v;
            Ot[t*STR + 2*j+1] = v1 * c2v;
        }
    }
    __syncthreads();
    #pragma unroll 2
    for (int c = 0; c < CC; c++) {
        unsigned long long wp = bcast2(g_Wout2T[c*CC + t]);
        const ulonglong2* orow = (const ulonglong2*)&Ot[c*STR];
        #pragma unroll
        for (int q = 0; q < 16; q++) {
            ulonglong2 v = orow[q];
            yacc[2*q]   = ffma2(wp, v.x, yacc[2*q]);
            yacc[2*q+1] = ffma2(wp, v.y, yacc[2*q+1]);
        }
    }
    float cb = bout1[t] + bout2[t];
    float s = 0.f, ss = 0.f;
    float* op = g_xmid + ((size_t)b*CC + t)*PN + pix0;
    #pragma unroll
    for (int j = 0; j < 32; j++) {
        float2 a = unpk(yacc[j]);
        float v0 = a.x + cb + Xt[t*STR + 2*j];
        float v1 = a.y + cb + Xt[t*STR + 2*j+1];
        op[2*j] = v0; op[2*j+1] = v1;
        s += v0 + v1; ss += v0*v0 + v1*v1;
    }
    rs[t] = s; rss[t] = ss; __syncthreads();
    for (int st = 128; st > 0; st >>= 1) {
        if (t < st) { rs[t] += rs[t+st]; rss[t] += rss[t+st]; }
        __syncthreads();
    }
    if (t == 0) { atomicAdd(&g_stats2[b*4+0], rs[0]); atomicAdd(&g_stats2[b*4+1], rss[0]); }
}

__global__ __launch_bounds__(256, 1)
void ffn_kernel(float* __restrict__ out, const float* __restrict__ bf2) {
    extern __shared__ float sm[];
    float* Xt = sm;
    float* Ht = sm + CC*STR;
    int blk  = blockIdx.x;
    int b    = blk >> 8;
    int pix0 = (blk & 255) * 64;
    int t    = threadIdx.x;
    float mu = g_stats2[b*4+2], inv = g_stats2[b*4+3];
    const float* xb = g_xmid + ((size_t)b*CC)*PN + pix0;
    for (int i = t; i < CC*64; i += 256) {
        int c = i >> 6, j = i & 63;
        Xt[c*STR + j] = xb[(size_t)c*PN + j];
    }
    __syncthreads();

    unsigned long long accA[32], accB[32];
    #pragma unroll
    for (int j = 0; j < 32; j++) { accA[j] = 0ULL; accB[j] = 0ULL; }
    #pragma unroll 2
    for (int c = 0; c < CC; c++) {
        unsigned long long wA = bcast2(g_Wf1GT[c*FF + t]);
        unsigned long long wB = bcast2(g_Wf1GT[c*FF + t + 256]);
        const ulonglong2* xr = (const ulonglong2*)&Xt[c*STR];
        #pragma unroll
        for (int q = 0; q < 16; q++) {
            ulonglong2 v = xr[q];
            accA[2*q]   = ffma2(wA, v.x, accA[2*q]);
            accA[2*q+1] = ffma2(wA, v.y, accA[2*q+1]);
            accB[2*q]   = ffma2(wB, v.x, accB[2*q]);
            accB[2*q+1] = ffma2(wB, v.y, accB[2*q+1]);
        }
    }
    {
        float dA = g_tbf1[t]       - inv*mu*g_Sf1[t];
        float dB = g_tbf1[t + 256] - inv*mu*g_Sf1[t + 256];
        #pragma unroll
        for (int j = 0; j < 32; j++) {
            float2 a = unpk(accA[j]);
            Ht[t*STR + 2*j]   = fminf(fmaxf(fmaf(inv, a.x, dA), -1.f), 1.f);
            Ht[t*STR + 2*j+1] = fminf(fmaxf(fmaf(inv, a.y, dA), -1.f), 1.f);
            float2 bm = unpk(accB[j]);
            Ht[(t+256)*STR + 2*j]   = fminf(fmaxf(fmaf(inv, bm.x, dB), -1.f), 1.f);
            Ht[(t+256)*STR + 2*j+1] = fminf(fmaxf(fmaf(inv, bm.y, dB), -1.f), 1.f);
        }
    }
    __syncthreads();
    unsigned long long yacc[32];
    #pragma unroll
    for (int j = 0; j < 32; j++) yacc[j] = 0ULL;
    #pragma unroll 2
    for (int f = 0; f < FF; f++) {
        unsigned long long wp = bcast2(g_Wf2T[f*CC + t]);
        const ulonglong2* hr = (const ulonglong2*)&Ht[f*STR];
        #pragma unroll
        for (int q = 0; q < 16; q++) {
            ulonglong2 v = hr[q];
            yacc[2*q]   = ffma2(wp, v.x, yacc[2*q]);
            yacc[2*q+1] = ffma2(wp, v.y, yacc[2*q+1]);
        }
    }
    float bo = bf2[t];
    float* op = out + ((size_t)b*CC + t)*PN + pix0;
    #pragma unroll
    for (int j = 0; j < 32; j++) {
        float2 a = unpk(yacc[j]);
        op[2*j]   = Xt[t*STR + 2*j]   + a.x + bo;
        op[2*j+1] = Xt[t*STR + 2*j+1] + a.y + bo;
    }
}

extern "C" void kernel_launch(void* const* d_in, const int* in_sizes, int n_in,
                              void* d_out, int out_size) {
    (void)in_sizes; (void)n_in; (void)out_size;
    const float* x     = (const float*)d_in[0];
    const float* g1    = (const float*)d_in[1];
    const float* b1    = (const float*)d_in[2];
    const float* Wqkv1 = (const float*)d_in[3];
    const float* bqkv1 = (const float*)d_in[4];
    const float* Wout1 = (const float*)d_in[5];
    const float* bout1 = (const float*)d_in[6];
    const float* g2    = (const float*)d_in[7];
    const float* b2    = (const float*)d_in[8];
    const float* Wqkv2 = (const float*)d_in[9];
    const float* bqkv2 = (const float*)d_in[10];
    const float* Wout2 = (const float*)d_in[11];
    const float* bout2 = (const float*)d_in[12];
    const float* gf    = (const float*)d_in[13];
    const float* bf    = (const float*)d_in[14];
    const float* Wf1   = (const float*)d_in[15];
    const float* bf1   = (const float*)d_in[16];
    const float* Wf2   = (const float*)d_in[17];
    const float* bf2   = (const float*)d_in[18];
    float* out = (float*)d_out;

    static_assert(2*CC*STR*4 == 139264, "attn smem");
    cudaFuncSetAttribute(ctx_kernel,  cudaFuncAttributeMaxDynamicSharedMemorySize, CC*64*4);
    cudaFuncSetAttribute(attn_kernel, cudaFuncAttributeMaxDynamicSharedMemorySize, 2*CC*STR*4);
    cudaFuncSetAttribute(ffn_kernel,  cudaFuncAttributeMaxDynamicSharedMemorySize, (CC+FF)*STR*4);

    zero_kernel<<<1, 64>>>();
    fold_kernel<<<2305, 256>>>(Wqkv1, bqkv1, g1, b1, Wqkv2, bqkv2, g2, b2,
                               Wf1, bf1, gf, bf, Wout1, Wout2, Wf2);
    qstats_kernel<<<BB*16, 256>>>(x);
    finalize_kernel<<<1, 32>>>(0);
    softmax_n_kernel<<<BB*PP, 256>>>();
    softmax_p_kernel<<<BB*NN, 64>>>();
    xs_kernel<<<BB*CC, 256>>>(x);
    ctx_kernel<<<BB*5, 256, CC*64*4>>>();
    attn_kernel<<<BB*256, 256, 2*CC*STR*4>>>(x, bout1, bout2);
    finalize_kernel<<<1, 32>>>(1);
    ffn_kernel<<<BB*256, 256, (CC+FF)*STR*4>>>(out, bf2);
}

// round 16
// speedup vs baseline: 1.1020x; 1.1020x over previous
#include <cuda_runtime.h>
#include <math.h>

#define BB 16
#define CC 256
#define PP 64
#define NN 256
#define PN 16384
#define FF 512
#define CPN (CC*PN)
#define STR 68

__device__ float g_WkG1T[CC*CC], g_WkG2T[CC*CC], g_WvG1T[CC*CC], g_WvG2T[CC*CC];
__device__ float g_Wout1T[CC*CC], g_Wout2T[CC*CC];
__device__ float g_Wf1GT[CC*FF];
__device__ float g_Wf2T[FF*CC];
__device__ float g_wq1[CC], g_wq2[CC];
__device__ float g_Sk1[CC], g_tbk1[CC], g_Sk2[CC], g_tbk2[CC];
__device__ float g_Sv1[CC], g_tbv1[CC], g_Sv2[CC], g_tbv2[CC];
__device__ float g_Sf1[FF], g_tbf1[FF];
__device__ float g_z1[BB*PN], g_z2[BB*PN];
__device__ float g_xs1[BB*CC*NN], g_xs2[BB*CC*PP];
__device__ float g_ctx1[BB*CC*NN], g_ctx2[BB*CC*PP];
__device__ float g_stats[BB*4], g_stats2[BB*4];
__device__ float g_xmid[(size_t)BB*CC*PN];

__device__ __forceinline__ unsigned long long ffma2(unsigned long long a,
                                                    unsigned long long b,
                                                    unsigned long long c) {
    unsigned long long d;
    asm("fma.rn.f32x2 %0, %1, %2, %3;" : "=l"(d) : "l"(a), "l"(b), "l"(c));
    return d;
}
__device__ __forceinline__ unsigned long long bcast2(float w) {
    unsigned long long r; unsigned u = __float_as_uint(w);
    asm("mov.b64 %0, {%1, %2};" : "=l"(r) : "r"(u), "r"(u));
    return r;
}
__device__ __forceinline__ float2 unpk(unsigned long long v) {
    unsigned lo, hi;
    asm("mov.b64 {%0, %1}, %2;" : "=r"(lo), "=r"(hi) : "l"(v));
    return make_float2(__uint_as_float(lo), __uint_as_float(hi));
}

__global__ void zero_kernel() {
    int t = threadIdx.x;
    if (t < BB*4) { g_stats[t] = 0.f; g_stats2[t] = 0.f; }
}

__global__ void fold_kernel(const float* __restrict__ Wqkv1, const float* __restrict__ bqkv1,
                            const float* __restrict__ g1,    const float* __restrict__ b1,
                            const float* __restrict__ Wqkv2, const float* __restrict__ bqkv2,
                            const float* __restrict__ g2,    const float* __restrict__ b2,
                            const float* __restrict__ Wf1,   const float* __restrict__ bf1,
                            const float* __restrict__ gf,    const float* __restrict__ bf,
                            const float* __restrict__ Wout1, const float* __restrict__ Wout2,
                            const float* __restrict__ Wf2) {
    int blk = blockIdx.x, t = threadIdx.x;
    __shared__ float red[256], red2[256];
    if (blk < 1024) {
        int sec = blk >> 8, o = blk & 255;
        const float *W, *bq, *g, *b; float *WT, *S, *TB; int row;
        if (sec == 0)      { W=Wqkv1; bq=bqkv1; g=g1; b=b1; WT=g_WkG1T; S=g_Sk1; TB=g_tbk1; row=1+o; }
        else if (sec == 1) { W=Wqkv1; bq=bqkv1; g=g1; b=b1; WT=g_WvG1T; S=g_Sv1; TB=g_tbv1; row=1+CC+o; }
        else if (sec == 2) { W=Wqkv2; bq=bqkv2; g=g2; b=b2; WT=g_WkG2T; S=g_Sk2; TB=g_tbk2; row=1+o; }
        else               { W=Wqkv2; bq=bqkv2; g=g2; b=b2; WT=g_WvG2T; S=g_Sv2; TB=g_tbv2; row=1+CC+o; }
        float w  = W[row*CC + t];
        float wg = w * g[t];
        WT[t*CC + o] = wg;
        red[t] = wg; red2[t] = w * b[t];
        __syncthreads();
        for (int s = 128; s > 0; s >>= 1) {
            if (t < s) { red[t] += red[t+s]; red2[t] += red2[t+s]; }
            __syncthreads();
        }
        if (t == 0) { S[o] = red[0]; TB[o] = red2[0] + bq[row]; }
    } else if (blk < 1536) {
        int f = blk - 1024;
        float w  = Wf1[f*CC + t];
        float wg = w * gf[t];
        g_Wf1GT[t*FF + f] = wg;
        red[t] = wg; red2[t] = w * bf[t];
        __syncthreads();
        for (int s = 128; s > 0; s >>= 1) {
            if (t < s) { red[t] += red[t+s]; red2[t] += red2[t+s]; }
            __syncthreads();
        }
        if (t == 0) { g_Sf1[f] = red[0]; g_tbf1[f] = red2[0] + bf1[f]; }
    } else if (blk < 1792) {
        int o = blk - 1536; g_Wout1T[t*CC + o] = Wout1[o*CC + t];
    } else if (blk < 2048) {
        int o = blk - 1792; g_Wout2T[t*CC + o] = Wout2[o*CC + t];
    } else if (blk < 2304) {
        int o = blk - 2048;
        g_Wf2T[t*CC + o]       = Wf2[o*FF + t];
        g_Wf2T[(t+256)*CC + o] = Wf2[o*FF + t + 256];
    } else {
        g_wq1[t] = Wqkv1[t] * g1[t];
        g_wq2[t] = Wqkv2[t] * g2[t];
    }
}

__global__ void qstats_kernel(const float* __restrict__ x) {
    int b    = blockIdx.x >> 4;
    int pix0 = (blockIdx.x & 15) * 1024;
    int t    = threadIdx.x;
    __shared__ float sw1[CC], sw2[CC];
    sw1[t] = g_wq1[t]; sw2[t] = g_wq2[t];
    __syncthreads();
    const float* xb = x + (size_t)b*CPN + pix0 + t*4;
    float a1x=0,a1y=0,a1z=0,a1w=0, a2x=0,a2y=0,a2z=0,a2w=0, s=0, ss=0;
    for (int c = 0; c < CC; c++) {
        float4 v = *(const float4*)(xb + (size_t)c*PN);
        float w1 = sw1[c], w2 = sw2[c];
        a1x = fmaf(w1,v.x,a1x); a1y = fmaf(w1,v.y,a1y); a1z = fmaf(w1,v.z,a1z); a1w = fmaf(w1,v.w,a1w);
        a2x = fmaf(w2,v.x,a2x); a2y = fmaf(w2,v.y,a2y); a2z = fmaf(w2,v.z,a2z); a2w = fmaf(w2,v.w,a2w);
        s  += v.x + v.y + v.z + v.w;
        ss += v.x*v.x + v.y*v.y + v.z*v.z + v.w*v.w;
    }
    size_t o = (size_t)b*PN + pix0 + t*4;
    *(float4*)(g_z1 + o) = make_float4(a1x,a1y,a1z,a1w);
    *(float4*)(g_z2 + o) = make_float4(a2x,a2y,a2z,a2w);
    __shared__ float rs[256], rss[256];
    rs[t] = s; rss[t] = ss; __syncthreads();
    for (int st = 128; st > 0; st >>= 1) {
        if (t < st) { rs[t] += rs[t+st]; rss[t] += rss[t+st]; }
        __syncthreads();
    }
    if (t == 0) { atomicAdd(&g_stats[b*4+0], rs[0]); atomicAdd(&g_stats[b*4+1], rss[0]); }
}

__global__ void finalize_kernel(int which) {
    float* st = which ? g_stats2 : g_stats;
    int t = threadIdx.x;
    if (t < BB) {
        float mu  = st[t*4+0] * (1.0f/(float)CPN);
        float var = st[t*4+1] * (1.0f/(float)CPN) - mu*mu;
        st[t*4+2] = mu;
        st[t*4+3] = rsqrtf(var + 1e-5f);
    }
}

__global__ void softmax_n_kernel() {
    int b = blockIdx.x / PP, p = blockIdx.x % PP, t = threadIdx.x;
    float inv = g_stats[b*4+3];
    float* z = g_z2 + (size_t)b*PN + p*NN;
    __shared__ float red[256];
    float v = z[t] * inv;
    red[t] = v; __syncthreads();
    for (int s = 128; s > 0; s >>= 1) { if (t < s) red[t] = fmaxf(red[t], red[t+s]); __syncthreads(); }
    float m = red[0]; __syncthreads();
    float e = expf(v - m);
    red[t] = e; __syncthreads();
    for (int s = 128; s > 0; s >>= 1) { if (t < s) red[t] += red[t+s]; __syncthreads(); }
    z[t] = e / red[0];
}

__global__ void softmax_p_kernel() {
    int b = blockIdx.x / NN, n = blockIdx.x % NN, t = threadIdx.x;
    float inv = g_stats[b*4+3];
    float* z = g_z1 + (size_t)b*PN + n;
    __shared__ float red[64];
    float v = z[t*NN] * inv;
    red[t] = v; __syncthreads();
    for (int s = 32; s > 0; s >>= 1) { if (t < s) red[t] = fmaxf(red[t], red[t+s]); __syncthreads(); }
    float m = red[0]; __syncthreads();
    float e = expf(v - m);
    red[t] = e; __syncthreads();
    for (int s = 32; s > 0; s >>= 1) { if (t < s) red[t] += red[t+s]; __syncthreads(); }
    z[t*NN] = e / red[0];
}

// warp-per-p-row; one block sync total
__global__ void xs_kernel(const float* __restrict__ x) {
    int b = blockIdx.x >> 8, c = blockIdx.x & 255;
    int t = threadIdx.x, w = t >> 5, l = t & 31;
    const float* xc = x    + ((size_t)b*CC + c)*PN;
    const float* s1 = g_z1 + (size_t)b*PN;
    const float* s2 = g_z2 + (size_t)b*PN;
    __shared__ float part1[8][256];
    __shared__ float out2[PP];
    float a1[8];
    #pragma unroll
    for (int k = 0; k < 8; k++) a1[k] = 0.f;
    for (int p = w; p < PP; p += 8) {
        float pr = 0.f;
        #pragma unroll
        for (int k = 0; k < 8; k++) {
            int n = l + 32*k;
            float v = xc[p*NN + n];
            a1[k] = fmaf(v, s1[p*NN + n], a1[k]);
            pr    = fmaf(v, s2[p*NN + n], pr);
        }
        for (int o = 16; o > 0; o >>= 1) pr += __shfl_down_sync(0xffffffffu, pr, o);
        if (l == 0) out2[p] = pr;
    }
    #pragma unroll
    for (int k = 0; k < 8; k++) part1[w][l + 32*k] = a1[k];
    __syncthreads();
    float s = 0.f;
    #pragma unroll
    for (int ww = 0; ww < 8; ww++) s += part1[ww][t];
    g_xs1[((size_t)b*CC + c)*NN + t] = s;
    if (t < PP) g_xs2[((size_t)b*CC + c)*PP + t] = out2[t];
}

__global__ void ctx_kernel() {
    extern __shared__ float Xs[];
    int b = blockIdx.x / 5, tile = blockIdx.x % 5, t = threadIdx.x;
    float mu = g_stats[b*4+2], inv = g_stats[b*4+3];
    const float *in, *WT, *S, *TB; float* out; int stride;
    if (tile < 4) {
        in  = g_xs1  + ((size_t)b*CC)*NN + tile*64;
        out = g_ctx1 + ((size_t)b*CC)*NN + tile*64;
        WT = g_WkG1T; S = g_Sk1; TB = g_tbk1; stride = NN;
    } else {
        in  = g_xs2  + ((size_t)b*CC)*PP;
        out = g_ctx2 + ((size_t)b*CC)*PP;
        WT = g_WkG2T; S = g_Sk2; TB = g_tbk2; stride = PP;
    }
    for (int i = t; i < CC*64; i += 256) {
        int c = i >> 6, j = i & 63;
        Xs[i] = in[(size_t)c*stride + j];
    }
    __syncthreads();
    float acc[64];
    #pragma unroll
    for (int j = 0; j < 64; j++) acc[j] = 0.f;
    for (int c = 0; c < CC; c++) {
        float w = WT[c*CC + t];
        const float* xr = &Xs[c*64];
        #pragma unroll
        for (int j = 0; j < 64; j++) acc[j] = fmaf(w, xr[j], acc[j]);
    }
    float d = TB[t] - inv*mu*S[t];
    for (int j = 0; j < 64; j++) out[(size_t)t*stride + j] = fmaf(inv, acc[j], d);
}

// 512 threads: thread = (channel ch, pixel-half h). 16 packed accumulators each.
__global__ __launch_bounds__(512, 1)
void attn_kernel(const float* __restrict__ x,
                 const float* __restrict__ bout1, const float* __restrict__ bout2) {
    extern __shared__ float sm[];
    float* Xt = sm;
    float* Ot = sm + CC*STR;
    __shared__ float rs[512], rss[512];
    int blk  = blockIdx.x;
    int b    = blk >> 8;
    int pix0 = (blk & 255) * 64;
    int p    = pix0 >> 8;
    int n0   = pix0 & 255;
    int t    = threadIdx.x;
    int ch   = t & 255;
    int h    = t >> 8;          // 0 or 1: pixel half
    int hb   = h * 32;
    float mu = g_stats[b*4+2], inv = g_stats[b*4+3];
    const float* xb = x + ((size_t)b*CC)*PN + pix0;
    for (int i = t; i < CC*64; i += 512) {
        int c = i >> 6, j = i & 63;
        Xt[c*STR + j] = xb[(size_t)c*PN + j];
    }
    __syncthreads();

    unsigned long long acc[16], yacc[16];
    // ---- V1 ----
    #pragma unroll
    for (int j = 0; j < 16; j++) acc[j] = 0ULL;
    #pragma unroll 2
    for (int c = 0; c < CC; c++) {
        unsigned long long wp = bcast2(g_WvG1T[c*CC + ch]);
        const ulonglong2* xr = (const ulonglong2*)&Xt[c*STR + hb];
        #pragma unroll
        for (int q = 0; q < 8; q++) {
            ulonglong2 v = xr[q];
            acc[2*q]   = ffma2(wp, v.x, acc[2*q]);
            acc[2*q+1] = ffma2(wp, v.y, acc[2*q+1]);
        }
    }
    {
        float d = g_tbv1[ch] - inv*mu*g_Sv1[ch];
        const float* c1 = g_ctx1 + ((size_t)b*CC + ch)*NN + n0 + hb;
        #pragma unroll
        for (int j = 0; j < 16; j++) {
            float2 a = unpk(acc[j]);
            float v0 = fmaxf(fmaf(inv, a.x, d), 0.f);
            float v1 = fmaxf(fmaf(inv, a.y, d), 0.f);
            Ot[ch*STR + hb + 2*j]   = v0 * c1[2*j];
            Ot[ch*STR + hb + 2*j+1] = v1 * c1[2*j+1];
        }
    }
    __syncthreads();
    // ---- Y = Wout1 @ O1 ----
    #pragma unroll
    for (int j = 0; j < 16; j++) yacc[j] = 0ULL;
    #pragma unroll 2
    for (int c = 0; c < CC; c++) {
        unsigned long long wp = bcast2(g_Wout1T[c*CC + ch]);
        const ulonglong2* orow = (const ulonglong2*)&Ot[c*STR + hb];
        #pragma unroll
        for (int q = 0; q < 8; q++) {
            ulonglong2 v = orow[q];
            yacc[2*q]   = ffma2(wp, v.x, yacc[2*q]);
            yacc[2*q+1] = ffma2(wp, v.y, yacc[2*q+1]);
        }
    }
    __syncthreads();
    // ---- V2 ----
    #pragma unroll
    for (int j = 0; j < 16; j++) acc[j] = 0ULL;
    #pragma unroll 2
    for (int c = 0; c < CC; c++) {
        unsigned long long wp = bcast2(g_WvG2T[c*CC + ch]);
        const ulonglong2* xr = (const ulonglong2*)&Xt[c*STR + hb];
        #pragma unroll
        for (int q = 0; q < 8; q++) {
            ulonglong2 v = xr[q];
            acc[2*q]   = ffma2(wp, v.x, acc[2*q]);
            acc[2*q+1] = ffma2(wp, v.y, acc[2*q+1]);
        }
    }
    {
        float d   = g_tbv2[ch] - inv*mu*g_Sv2[ch];
        float c2v = g_ctx2[((size_t)b*CC + ch)*PP + p];
        #pragma unroll
        for (int j = 0; j < 16; j++) {
            float2 a = unpk(acc[j]);
            float v0 = fmaxf(fmaf(inv, a.x, d), 0.f);
            float v1 = fmaxf(fmaf(inv, a.y, d), 0.f);
            Ot[ch*STR + hb + 2*j]   = v0 * c2v;
            Ot[ch*STR + hb + 2*j+1] = v1 * c2v;
        }
    }
    __syncthreads();
    // ---- Y += Wout2 @ O2 ----
    #pragma unroll 2
    for (int c = 0; c < CC; c++) {
        unsigned long long wp = bcast2(g_Wout2T[c*CC + ch]);
        const ulonglong2* orow = (const ulonglong2*)&Ot[c*STR + hb];
        #pragma unroll
        for (int q = 0; q < 8; q++) {
            ulonglong2 v = orow[q];
            yacc[2*q]   = ffma2(wp, v.x, yacc[2*q]);
            yacc[2*q+1] = ffma2(wp, v.y, yacc[2*q+1]);
        }
    }
    float cb = bout1[ch] + bout2[ch];
    float s = 0.f, ss = 0.f;
    float* op = g_xmid + ((size_t)b*CC + ch)*PN + pix0 + hb;
    #pragma unroll
    for (int j = 0; j < 16; j++) {
        float2 a = unpk(yacc[j]);
        float v0 = a.x + cb + Xt[ch*STR + hb + 2*j];
        float v1 = a.y + cb + Xt[ch*STR + hb + 2*j+1];
        op[2*j] = v0; op[2*j+1] = v1;
        s += v0 + v1; ss += v0*v0 + v1*v1;
    }
    rs[t] = s; rss[t] = ss; __syncthreads();
    for (int st = 256; st > 0; st >>= 1) {
        if (t < st) { rs[t] += rs[t+st]; rss[t] += rss[t+st]; }
        __syncthreads();
    }
    if (t == 0) { atomicAdd(&g_stats2[b*4+0], rs[0]); atomicAdd(&g_stats2[b*4+1], rss[0]); }
}

// 512 threads: phase1 thread = f-channel (64 px); phase2 thread = (ch, half).
__global__ __launch_bounds__(512, 1)
void ffn_kernel(float* __restrict__ out, const float* __restrict__ bf2) {
    extern __shared__ float sm[];
    float* Xt = sm;
    float* Ht = sm + CC*STR;
    int blk  = blockIdx.x;
    int b    = blk >> 8;
    int pix0 = (blk & 255) * 64;
    int t    = threadIdx.x;
    int ch   = t & 255;
    int h    = t >> 8;
    int hb   = h * 32;
    float mu = g_stats2[b*4+2], inv = g_stats2[b*4+3];
    const float* xb = g_xmid + ((size_t)b*CC)*PN + pix0;
    for (int i = t; i < CC*64; i += 512) {
        int c = i >> 6, j = i & 63;
        Xt[c*STR + j] = xb[(size_t)c*PN + j];
    }
    __syncthreads();

    // phase 1: H[t][0..63], t = f-channel
    {
        unsigned long long acc[32];
        #pragma unroll
        for (int j = 0; j < 32; j++) acc[j] = 0ULL;
        #pragma unroll 2
        for (int c = 0; c < CC; c++) {
            unsigned long long wp = bcast2(g_Wf1GT[c*FF + t]);
            const ulonglong2* xr = (const ulonglong2*)&Xt[c*STR];
            #pragma unroll
            for (int q = 0; q < 16; q++) {
                ulonglong2 v = xr[q];
                acc[2*q]   = ffma2(wp, v.x, acc[2*q]);
                acc[2*q+1] = ffma2(wp, v.y, acc[2*q+1]);
            }
        }
        float d = g_tbf1[t] - inv*mu*g_Sf1[t];
        #pragma unroll
        for (int j = 0; j < 32; j++) {
            float2 a = unpk(acc[j]);
            Ht[t*STR + 2*j]   = fminf(fmaxf(fmaf(inv, a.x, d), -1.f), 1.f);
            Ht[t*STR + 2*j+1] = fminf(fmaxf(fmaf(inv, a.y, d), -1.f), 1.f);
        }
    }
    __syncthreads();
    // phase 2: out = Wf2 @ H + x
    unsigned long long yacc[16];
    #pragma unroll
    for (int j = 0; j < 16; j++) yacc[j] = 0ULL;
    #pragma unroll 2
    for (int f = 0; f < FF; f++) {
        unsigned long long wp = bcast2(g_Wf2T[f*CC + ch]);
        const ulonglong2* hr = (const ulonglong2*)&Ht[f*STR + hb];
        #pragma unroll
        for (int q = 0; q < 8; q++) {
            ulonglong2 v = hr[q];
            yacc[2*q]   = ffma2(wp, v.x, yacc[2*q]);
            yacc[2*q+1] = ffma2(wp, v.y, yacc[2*q+1]);
        }
    }
    float bo = bf2[ch];
    float* op = out + ((size_t)b*CC + ch)*PN + pix0 + hb;
    #pragma unroll
    for (int j = 0; j < 16; j++) {
        float2 a = unpk(yacc[j]);
        op[2*j]   = Xt[ch*STR + hb + 2*j]   + a.x + bo;
        op[2*j+1] = Xt[ch*STR + hb + 2*j+1] + a.y + bo;
    }
}

extern "C" void kernel_launch(void* const* d_in, const int* in_sizes, int n_in,
                              void* d_out, int out_size) {
    (void)in_sizes; (void)n_in; (void)out_size;
    const float* x     = (const float*)d_in[0];
    const float* g1    = (const float*)d_in[1];
    const float* b1    = (const float*)d_in[2];
    const float* Wqkv1 = (const float*)d_in[3];
    const float* bqkv1 = (const float*)d_in[4];
    const float* Wout1 = (const float*)d_in[5];
    const float* bout1 = (const float*)d_in[6];
    const float* g2    = (const float*)d_in[7];
    const float* b2    = (const float*)d_in[8];
    const float* Wqkv2 = (const float*)d_in[9];
    const float* bqkv2 = (const float*)d_in[10];
    const float* Wout2 = (const float*)d_in[11];
    const float* bout2 = (const float*)d_in[12];
    const float* gf    = (const float*)d_in[13];
    const float* bf    = (const float*)d_in[14];
    const float* Wf1   = (const float*)d_in[15];
    const float* bf1   = (const float*)d_in[16];
    const float* Wf2   = (const float*)d_in[17];
    const float* bf2   = (const float*)d_in[18];
    float* out = (float*)d_out;

    cudaFuncSetAttribute(ctx_kernel,  cudaFuncAttributeMaxDynamicSharedMemorySize, CC*64*4);
    cudaFuncSetAttribute(attn_kernel, cudaFuncAttributeMaxDynamicSharedMemorySize, 2*CC*STR*4);
    cudaFuncSetAttribute(ffn_kernel,  cudaFuncAttributeMaxDynamicSharedMemorySize, (CC+FF)*STR*4);

    zero_kernel<<<1, 64>>>();
    fold_kernel<<<2305, 256>>>(Wqkv1, bqkv1, g1, b1, Wqkv2, bqkv2, g2, b2,
                               Wf1, bf1, gf, bf, Wout1, Wout2, Wf2);
    qstats_kernel<<<BB*16, 256>>>(x);
    finalize_kernel<<<1, 32>>>(0);
    softmax_n_kernel<<<BB*PP, 256>>>();
    softmax_p_kernel<<<BB*NN, 64>>>();
    xs_kernel<<<BB*CC, 256>>>(x);
    ctx_kernel<<<BB*5, 256, CC*64*4>>>();
    attn_kernel<<<BB*256, 512, 2*CC*STR*4>>>(x, bout1, bout2);
    finalize_kernel<<<1, 32>>>(1);
    ffn_kernel<<<BB*256, 512, (CC+FF)*STR*4>>>(out, bf2);
}

// round 17
// speedup vs baseline: 1.4858x; 1.3482x over previous
#include <cuda_runtime.h>
#include <math.h>

#define BB 16
#define CC 256
#define PP 64
#define NN 256
#define PN 16384
#define FF 512
#define CPN (CC*PN)
#define STR 68

__device__ float g_WkG1T[CC*CC], g_WkG2T[CC*CC], g_WvG1T[CC*CC], g_WvG2T[CC*CC];
__device__ float g_Wout1T[CC*CC], g_Wout2T[CC*CC];
__device__ float g_Wf1GT[CC*FF];
__device__ float g_Wf2T[FF*CC];
__device__ float g_wq1[CC], g_wq2[CC];
__device__ float g_Sk1[CC], g_tbk1[CC], g_Sk2[CC], g_tbk2[CC];
__device__ float g_Sv1[CC], g_tbv1[CC], g_Sv2[CC], g_tbv2[CC];
__device__ float g_Sf1[FF], g_tbf1[FF];
__device__ float g_z1[BB*PN], g_z2[BB*PN];
__device__ float g_xs1[BB*CC*NN], g_xs2[BB*CC*PP];
__device__ float g_ctx1[BB*CC*NN], g_ctx2[BB*CC*PP];
__device__ float g_stats[BB*4], g_stats2[BB*4];
__device__ float g_xmid[(size_t)BB*CC*PN];

__device__ __forceinline__ unsigned long long ffma2(unsigned long long a,
                                                    unsigned long long b,
                                                    unsigned long long c) {
    unsigned long long d;
    asm("fma.rn.f32x2 %0, %1, %2, %3;" : "=l"(d) : "l"(a), "l"(b), "l"(c));
    return d;
}
__device__ __forceinline__ unsigned long long bcast2(float w) {
    unsigned long long r; unsigned u = __float_as_uint(w);
    asm("mov.b64 %0, {%1, %2};" : "=l"(r) : "r"(u), "r"(u));
    return r;
}
__device__ __forceinline__ float2 unpk(unsigned long long v) {
    unsigned lo, hi;
    asm("mov.b64 {%0, %1}, %2;" : "=r"(lo), "=r"(hi) : "l"(v));
    return make_float2(__uint_as_float(lo), __uint_as_float(hi));
}
__device__ __forceinline__ void sample_stats(const float* st, int b, float& mu, float& inv) {
    float s0 = st[b*4+0], s1 = st[b*4+1];
    mu  = s0 * (1.0f/(float)CPN);
    inv = rsqrtf(s1 * (1.0f/(float)CPN) - mu*mu + 1e-5f);
}

// GEMM over smem SRC (stride STR), 4 out-channels ch0..ch0+3, 8 pixels at px0.
// Weight Wmat has stride CC (out-channel-minor). Accumulates into ACC[16].
#define GEMM4x8(Wmat, SRC, ACC, KDIM) \
    { _Pragma("unroll 4") \
      for (int c_ = 0; c_ < (KDIM); c_++) { \
        float4 w4_ = *(const float4*)&Wmat[c_*CC + ch0]; \
        unsigned long long w0_=bcast2(w4_.x), w1_=bcast2(w4_.y), w2_=bcast2(w4_.z), w3_=bcast2(w4_.w); \
        const ulonglong2* xr_ = (const ulonglong2*)&SRC[c_*STR + px0]; \
        ulonglong2 xa_ = xr_[0], xb_ = xr_[1]; \
        ACC[0] =ffma2(w0_,xa_.x,ACC[0]);  ACC[1] =ffma2(w0_,xa_.y,ACC[1]);  ACC[2] =ffma2(w0_,xb_.x,ACC[2]);  ACC[3] =ffma2(w0_,xb_.y,ACC[3]); \
        ACC[4] =ffma2(w1_,xa_.x,ACC[4]);  ACC[5] =ffma2(w1_,xa_.y,ACC[5]);  ACC[6] =ffma2(w1_,xb_.x,ACC[6]);  ACC[7] =ffma2(w1_,xb_.y,ACC[7]); \
        ACC[8] =ffma2(w2_,xa_.x,ACC[8]);  ACC[9] =ffma2(w2_,xa_.y,ACC[9]);  ACC[10]=ffma2(w2_,xb_.x,ACC[10]); ACC[11]=ffma2(w2_,xb_.y,ACC[11]); \
        ACC[12]=ffma2(w3_,xa_.x,ACC[12]); ACC[13]=ffma2(w3_,xa_.y,ACC[13]); ACC[14]=ffma2(w3_,xb_.x,ACC[14]); ACC[15]=ffma2(w3_,xb_.y,ACC[15]); \
      } }

__global__ void fold_kernel(const float* __restrict__ Wqkv1, const float* __restrict__ bqkv1,
                            const float* __restrict__ g1,    const float* __restrict__ b1,
                            const float* __restrict__ Wqkv2, const float* __restrict__ bqkv2,
                            const float* __restrict__ g2,    const float* __restrict__ b2,
                            const float* __restrict__ Wf1,   const float* __restrict__ bf1,
                            const float* __restrict__ gf,    const float* __restrict__ bf,
                            const float* __restrict__ Wout1, const float* __restrict__ Wout2,
                            const float* __restrict__ Wf2) {
    int blk = blockIdx.x, t = threadIdx.x;
    __shared__ float red[256], red2[256];
    if (blk < 1024) {
        int sec = blk >> 8, o = blk & 255;
        const float *W, *bq, *g, *b; float *WT, *S, *TB; int row;
        if (sec == 0)      { W=Wqkv1; bq=bqkv1; g=g1; b=b1; WT=g_WkG1T; S=g_Sk1; TB=g_tbk1; row=1+o; }
        else if (sec == 1) { W=Wqkv1; bq=bqkv1; g=g1; b=b1; WT=g_WvG1T; S=g_Sv1; TB=g_tbv1; row=1+CC+o; }
        else if (sec == 2) { W=Wqkv2; bq=bqkv2; g=g2; b=b2; WT=g_WkG2T; S=g_Sk2; TB=g_tbk2; row=1+o; }
        else               { W=Wqkv2; bq=bqkv2; g=g2; b=b2; WT=g_WvG2T; S=g_Sv2; TB=g_tbv2; row=1+CC+o; }
        float w  = W[row*CC + t];
        float wg = w * g[t];
        WT[t*CC + o] = wg;
        red[t] = wg; red2[t] = w * b[t];
        __syncthreads();
        for (int s = 128; s > 0; s >>= 1) {
            if (t < s) { red[t] += red[t+s]; red2[t] += red2[t+s]; }
            __syncthreads();
        }
        if (t == 0) { S[o] = red[0]; TB[o] = red2[0] + bq[row]; }
    } else if (blk < 1536) {
        int f = blk - 1024;
        float w  = Wf1[f*CC + t];
        float wg = w * gf[t];
        g_Wf1GT[t*FF + f] = wg;
        red[t] = wg; red2[t] = w * bf[t];
        __syncthreads();
        for (int s = 128; s > 0; s >>= 1) {
            if (t < s) { red[t] += red[t+s]; red2[t] += red2[t+s]; }
            __syncthreads();
        }
        if (t == 0) { g_Sf1[f] = red[0]; g_tbf1[f] = red2[0] + bf1[f]; }
    } else if (blk < 1792) {
        int o = blk - 1536; g_Wout1T[t*CC + o] = Wout1[o*CC + t];
    } else if (blk < 2048) {
        int o = blk - 1792; g_Wout2T[t*CC + o] = Wout2[o*CC + t];
    } else if (blk < 2304) {
        int o = blk - 2048;
        g_Wf2T[t*CC + o]       = Wf2[o*FF + t];
        g_Wf2T[(t+256)*CC + o] = Wf2[o*FF + t + 256];
    } else {
        g_wq1[t] = Wqkv1[t] * g1[t];
        g_wq2[t] = Wqkv2[t] * g2[t];
        if (t < BB*4) { g_stats[t] = 0.f; g_stats2[t] = 0.f; }
    }
}

__global__ void qstats_kernel(const float* __restrict__ x) {
    int b    = blockIdx.x >> 4;
    int pix0 = (blockIdx.x & 15) * 1024;
    int t    = threadIdx.x;
    __shared__ float sw1[CC], sw2[CC];
    sw1[t] = g_wq1[t]; sw2[t] = g_wq2[t];
    __syncthreads();
    const float* xb = x + (size_t)b*CPN + pix0 + t*4;
    float a1x=0,a1y=0,a1z=0,a1w=0, a2x=0,a2y=0,a2z=0,a2w=0, s=0, ss=0;
    for (int c = 0; c < CC; c++) {
        float4 v = *(const float4*)(xb + (size_t)c*PN);
        float w1 = sw1[c], w2 = sw2[c];
        a1x = fmaf(w1,v.x,a1x); a1y = fmaf(w1,v.y,a1y); a1z = fmaf(w1,v.z,a1z); a1w = fmaf(w1,v.w,a1w);
        a2x = fmaf(w2,v.x,a2x); a2y = fmaf(w2,v.y,a2y); a2z = fmaf(w2,v.z,a2z); a2w = fmaf(w2,v.w,a2w);
        s  += v.x + v.y + v.z + v.w;
        ss += v.x*v.x + v.y*v.y + v.z*v.z + v.w*v.w;
    }
    size_t o = (size_t)b*PN + pix0 + t*4;
    *(float4*)(g_z1 + o) = make_float4(a1x,a1y,a1z,a1w);
    *(float4*)(g_z2 + o) = make_float4(a2x,a2y,a2z,a2w);
    __shared__ float rs[256], rss[256];
    rs[t] = s; rss[t] = ss; __syncthreads();
    for (int st = 128; st > 0; st >>= 1) {
        if (t < st) { rs[t] += rs[t+st]; rss[t] += rss[t+st]; }
        __syncthreads();
    }
    if (t == 0) { atomicAdd(&g_stats[b*4+0], rs[0]); atomicAdd(&g_stats[b*4+1], rss[0]); }
}

// blocks [0, BB*PP): softmax over n (rows of 256). blocks [BB*PP, BB*PP+BB*64): softmax over p (4 cols per block).
__global__ void softmax_np_kernel() {
    int blk = blockIdx.x, t = threadIdx.x;
    if (blk < BB*PP) {
        int b = blk / PP, p = blk % PP;
        float mu, inv; sample_stats(g_stats, b, mu, inv); (void)mu;
        float* z = g_z2 + (size_t)b*PN + p*NN;
        __shared__ float red[256];
        float v = z[t] * inv;
        red[t] = v; __syncthreads();
        for (int s = 128; s > 0; s >>= 1) { if (t < s) red[t] = fmaxf(red[t], red[t+s]); __syncthreads(); }
        float m = red[0]; __syncthreads();
        float e = expf(v - m);
        red[t] = e; __syncthreads();
        for (int s = 128; s > 0; s >>= 1) { if (t < s) red[t] += red[t+s]; __syncthreads(); }
        z[t] = e / red[0];
    } else {
        int i = blk - BB*PP;
        int b = i >> 6, ng = i & 63;
        int sub = t >> 6, tp = t & 63;
        int n = ng*4 + sub;
        float mu, inv; sample_stats(g_stats, b, mu, inv); (void)mu;
        float* z = g_z1 + (size_t)b*PN + n;
        __shared__ float red[4][64];
        float v = z[tp*NN] * inv;
        red[sub][tp] = v; __syncthreads();
        for (int s = 32; s > 0; s >>= 1) { if (tp < s) red[sub][tp] = fmaxf(red[sub][tp], red[sub][tp+s]); __syncthreads(); }
        float m = red[sub][0]; __syncthreads();
        float e = expf(v - m);
        red[sub][tp] = e; __syncthreads();
        for (int s = 32; s > 0; s >>= 1) { if (tp < s) red[sub][tp] += red[sub][tp+s]; __syncthreads(); }
        z[tp*NN] = e / red[sub][0];
    }
}

__global__ void xs_kernel(const float* __restrict__ x) {
    int b = blockIdx.x >> 8, c = blockIdx.x & 255;
    int t = threadIdx.x, w = t >> 5, l = t & 31;
    const float* xc = x    + ((size_t)b*CC + c)*PN;
    const float* s1 = g_z1 + (size_t)b*PN;
    const float* s2 = g_z2 + (size_t)b*PN;
    __shared__ float part1[8][256];
    __shared__ float out2[PP];
    float a1[8];
    #pragma unroll
    for (int k = 0; k < 8; k++) a1[k] = 0.f;
    for (int p = w; p < PP; p += 8) {
        float pr = 0.f;
        #pragma unroll
        for (int k = 0; k < 8; k++) {
            int n = l + 32*k;
            float v = xc[p*NN + n];
            a1[k] = fmaf(v, s1[p*NN + n], a1[k]);
            pr    = fmaf(v, s2[p*NN + n], pr);
        }
        for (int o = 16; o > 0; o >>= 1) pr += __shfl_down_sync(0xffffffffu, pr, o);
        if (l == 0) out2[p] = pr;
    }
    #pragma unroll
    for (int k = 0; k < 8; k++) part1[w][l + 32*k] = a1[k];
    __syncthreads();
    float s = 0.f;
    #pragma unroll
    for (int ww = 0; ww < 8; ww++) s += part1[ww][t];
    g_xs1[((size_t)b*CC + c)*NN + t] = s;
    if (t < PP) g_xs2[((size_t)b*CC + c)*PP + t] = out2[t];
}

__global__ void ctx_kernel() {
    extern __shared__ float Xs[];
    int b = blockIdx.x / 5, tile = blockIdx.x % 5, t = threadIdx.x;
    float mu, inv; sample_stats(g_stats, b, mu, inv);
    const float *in, *WT, *S, *TB; float* out; int stride;
    if (tile < 4) {
        in  = g_xs1  + ((size_t)b*CC)*NN + tile*64;
        out = g_ctx1 + ((size_t)b*CC)*NN + tile*64;
        WT = g_WkG1T; S = g_Sk1; TB = g_tbk1; stride = NN;
    } else {
        in  = g_xs2  + ((size_t)b*CC)*PP;
        out = g_ctx2 + ((size_t)b*CC)*PP;
        WT = g_WkG2T; S = g_Sk2; TB = g_tbk2; stride = PP;
    }
    for (int i = t; i < CC*64; i += 256) {
        int c = i >> 6, j = i & 63;
        Xs[i] = in[(size_t)c*stride + j];
    }
    __syncthreads();
    float acc[64];
    #pragma unroll
    for (int j = 0; j < 64; j++) acc[j] = 0.f;
    for (int c = 0; c < CC; c++) {
        float w = WT[c*CC + t];
        const float* xr = &Xs[c*64];
        #pragma unroll
        for (int j = 0; j < 64; j++) acc[j] = fmaf(w, xr[j], acc[j]);
    }
    float d = TB[t] - inv*mu*S[t];
    for (int j = 0; j < 64; j++) out[(size_t)t*stride + j] = fmaf(inv, acc[j], d);
}

// 512 threads: thread = (ch-group of 4, pixel octet). acc/yacc: 16 u64 each.
__global__ __launch_bounds__(512, 1)
void attn_kernel(const float* __restrict__ x,
                 const float* __restrict__ bout1, const float* __restrict__ bout2) {
    extern __shared__ float sm[];
    float* Xt = sm;
    float* Ot = sm + CC*STR;
    __shared__ float rs[512], rss[512];
    int blk  = blockIdx.x;
    int b    = blk >> 8;
    int pix0 = (blk & 255) * 64;
    int p    = pix0 >> 8;
    int n0   = pix0 & 255;
    int t    = threadIdx.x;
    int ch0  = (t & 63) * 4;
    int px0  = (t >> 6) * 8;
    float mu, inv; sample_stats(g_stats, b, mu, inv);
    const float* xb = x + ((size_t)b*CC)*PN + pix0;
    for (int i = t; i < CC*64; i += 512) {
        int c = i >> 6, j = i & 63;
        Xt[c*STR + j] = xb[(size_t)c*PN + j];
    }
    __syncthreads();

    unsigned long long acc[16], yacc[16];
    // ---- V1 = WvG1 @ X ----
    #pragma unroll
    for (int j = 0; j < 16; j++) acc[j] = 0ULL;
    GEMM4x8(g_WvG1T, Xt, acc, CC);
    #pragma unroll
    for (int ci = 0; ci < 4; ci++) {
        int ch = ch0 + ci;
        float d = g_tbv1[ch] - inv*mu*g_Sv1[ch];
        const float* c1 = g_ctx1 + ((size_t)b*CC + ch)*NN + n0 + px0;
        float* od = &Ot[ch*STR + px0];
        #pragma unroll
        for (int k = 0; k < 4; k++) {
            float2 a = unpk(acc[ci*4 + k]);
            od[2*k]   = fmaxf(fmaf(inv, a.x, d), 0.f) * c1[2*k];
            od[2*k+1] = fmaxf(fmaf(inv, a.y, d), 0.f) * c1[2*k+1];
        }
    }
    __syncthreads();
    // ---- Y = Wout1 @ O1 ----
    #pragma unroll
    for (int j = 0; j < 16; j++) yacc[j] = 0ULL;
    GEMM4x8(g_Wout1T, Ot, yacc, CC);
    // ---- V2 = WvG2 @ X (reads Xt only; Ot still being read above by others -> sync before write) ----
    #pragma unroll
    for (int j = 0; j < 16; j++) acc[j] = 0ULL;
    GEMM4x8(g_WvG2T, Xt, acc, CC);
    __syncthreads();
    #pragma unroll
    for (int ci = 0; ci < 4; ci++) {
        int ch = ch0 + ci;
        float d   = g_tbv2[ch] - inv*mu*g_Sv2[ch];
        float c2v = g_ctx2[((size_t)b*CC + ch)*PP + p];
        float* od = &Ot[ch*STR + px0];
        #pragma unroll
        for (int k = 0; k < 4; k++) {
            float2 a = unpk(acc[ci*4 + k]);
            od[2*k]   = fmaxf(fmaf(inv, a.x, d), 0.f) * c2v;
            od[2*k+1] = fmaxf(fmaf(inv, a.y, d), 0.f) * c2v;
        }
    }
    __syncthreads();
    // ---- Y += Wout2 @ O2 ----
    GEMM4x8(g_Wout2T, Ot, yacc, CC);
    // ---- residual + bias + write + stats ----
    float s = 0.f, ss = 0.f;
    #pragma unroll
    for (int ci = 0; ci < 4; ci++) {
        int ch = ch0 + ci;
        float cb = bout1[ch] + bout2[ch];
        const float* xrow = &Xt[ch*STR + px0];
        float* op = g_xmid + ((size_t)b*CC + ch)*PN + pix0 + px0;
        float2 a0 = unpk(yacc[ci*4+0]);
        float2 a1 = unpk(yacc[ci*4+1]);
        float2 a2 = unpk(yacc[ci*4+2]);
        float2 a3 = unpk(yacc[ci*4+3]);
        float4 o0, o1;
        o0.x = a0.x + cb + xrow[0]; o0.y = a0.y + cb + xrow[1];
        o0.z = a1.x + cb + xrow[2]; o0.w = a1.y + cb + xrow[3];
        o1.x = a2.x + cb + xrow[4]; o1.y = a2.y + cb + xrow[5];
        o1.z = a3.x + cb + xrow[6]; o1.w = a3.y + cb + xrow[7];
        *(float4*)op = o0; *(float4*)(op+4) = o1;
        s  += o0.x+o0.y+o0.z+o0.w + o1.x+o1.y+o1.z+o1.w;
        ss += o0.x*o0.x+o0.y*o0.y+o0.z*o0.z+o0.w*o0.w
            + o1.x*o1.x+o1.y*o1.y+o1.z*o1.z+o1.w*o1.w;
    }
    rs[t] = s; rss[t] = ss; __syncthreads();
    for (int st = 256; st > 0; st >>= 1) {
        if (t < st) { rs[t] += rs[t+st]; rss[t] += rss[t+st]; }
        __syncthreads();
    }
    if (t == 0) { atomicAdd(&g_stats2[b*4+0], rs[0]); atomicAdd(&g_stats2[b*4+1], rss[0]); }
}

// 512 threads. phase1: 4 f-channels x 16 px; phase2: 4 ch x 8 px.
__global__ __launch_bounds__(512, 1)
void ffn_kernel(float* __restrict__ out, const float* __restrict__ bf2) {
    extern __shared__ float sm[];
    float* Xt = sm;
    float* Ht = sm + CC*STR;
    int blk  = blockIdx.x;
    int b    = blk >> 8;
    int pix0 = (blk & 255) * 64;
    int t    = threadIdx.x;
    float mu, inv; sample_stats(g_stats2, b, mu, inv);
    const float* xb = g_xmid + ((size_t)b*CC)*PN + pix0;
    for (int i = t; i < CC*64; i += 512) {
        int c = i >> 6, j = i & 63;
        Xt[c*STR + j] = xb[(size_t)c*PN + j];
    }
    __syncthreads();

    // phase 1: H = clip(inv*(Wf1G @ X) + d), 4 f x 16 px per thread
    {
        int f0  = (t & 127) * 4;
        int qx0 = (t >> 7) * 16;
        unsigned long long acc[32];
        #pragma unroll
        for (int j = 0; j < 32; j++) acc[j] = 0ULL;
        #pragma unroll 4
        for (int c = 0; c < CC; c++) {
            float4 w4 = *(const float4*)&g_Wf1GT[c*FF + f0];
            unsigned long long w0=bcast2(w4.x), w1=bcast2(w4.y), w2=bcast2(w4.z), w3=bcast2(w4.w);
            const ulonglong2* xr = (const ulonglong2*)&Xt[c*STR + qx0];
            ulonglong2 x0 = xr[0], x1 = xr[1], x2 = xr[2], x3 = xr[3];
            acc[0] =ffma2(w0,x0.x,acc[0]);  acc[1] =ffma2(w0,x0.y,acc[1]);  acc[2] =ffma2(w0,x1.x,acc[2]);  acc[3] =ffma2(w0,x1.y,acc[3]);
            acc[4] =ffma2(w0,x2.x,acc[4]);  acc[5] =ffma2(w0,x2.y,acc[5]);  acc[6] =ffma2(w0,x3.x,acc[6]);  acc[7] =ffma2(w0,x3.y,acc[7]);
            acc[8] =ffma2(w1,x0.x,acc[8]);  acc[9] =ffma2(w1,x0.y,acc[9]);  acc[10]=ffma2(w1,x1.x,acc[10]); acc[11]=ffma2(w1,x1.y,acc[11]);
            acc[12]=ffma2(w1,x2.x,acc[12]); acc[13]=ffma2(w1,x2.y,acc[13]); acc[14]=ffma2(w1,x3.x,acc[14]); acc[15]=ffma2(w1,x3.y,acc[15]);
            acc[16]=ffma2(w2,x0.x,acc[16]); acc[17]=ffma2(w2,x0.y,acc[17]); acc[18]=ffma2(w2,x1.x,acc[18]); acc[19]=ffma2(w2,x1.y,acc[19]);
            acc[20]=ffma2(w2,x2.x,acc[20]); acc[21]=ffma2(w2,x2.y,acc[21]); acc[22]=ffma2(w2,x3.x,acc[22]); acc[23]=ffma2(w2,x3.y,acc[23]);
            acc[24]=ffma2(w3,x0.x,acc[24]); acc[25]=ffma2(w3,x0.y,acc[25]); acc[26]=ffma2(w3,x1.x,acc[26]); acc[27]=ffma2(w3,x1.y,acc[27]);
            acc[28]=ffma2(w3,x2.x,acc[28]); acc[29]=ffma2(w3,x2.y,acc[29]); acc[30]=ffma2(w3,x3.x,acc[30]); acc[31]=ffma2(w3,x3.y,acc[31]);
        }
        #pragma unroll
        for (int fi = 0; fi < 4; fi++) {
            int f = f0 + fi;
            float d = g_tbf1[f] - inv*mu*g_Sf1[f];
            float* hd = &Ht[f*STR + qx0];
            #pragma unroll
            for (int k = 0; k < 8; k++) {
                float2 a = unpk(acc[fi*8 + k]);
                hd[2*k]   = fminf(fmaxf(fmaf(inv, a.x, d), -1.f), 1.f);
                hd[2*k+1] = fminf(fmaxf(fmaf(inv, a.y, d), -1.f), 1.f);
            }
        }
    }
    __syncthreads();
    // phase 2: out = Wf2 @ H + x + bf2, 4 ch x 8 px per thread
    {
        int ch0 = (t & 63) * 4;
        int px0 = (t >> 6) * 8;
        unsigned long long yacc[16];
        #pragma unroll
        for (int j = 0; j < 16; j++) yacc[j] = 0ULL;
        GEMM4x8(g_Wf2T, Ht, yacc, FF);
        #pragma unroll
        for (int ci = 0; ci < 4; ci++) {
            int ch = ch0 + ci;
            float bo = bf2[ch];
            const float* xrow = &Xt[ch*STR + px0];
            float* op = out + ((size_t)b*CC + ch)*PN + pix0 + px0;
            float2 a0 = unpk(yacc[ci*4+0]);
            float2 a1 = unpk(yacc[ci*4+1]);
            float2 a2 = unpk(yacc[ci*4+2]);
            float2 a3 = unpk(yacc[ci*4+3]);
            float4 o0, o1;
            o0.x = a0.x + bo + xrow[0]; o0.y = a0.y + bo + xrow[1];
            o0.z = a1.x + bo + xrow[2]; o0.w = a1.y + bo + xrow[3];
            o1.x = a2.x + bo + xrow[4]; o1.y = a2.y + bo + xrow[5];
            o1.z = a3.x + bo + xrow[6]; o1.w = a3.y + bo + xrow[7];
            *(float4*)op = o0; *(float4*)(op+4) = o1;
        }
    }
}

extern "C" void kernel_launch(void* const* d_in, const int* in_sizes, int n_in,
                              void* d_out, int out_size) {
    (void)in_sizes; (void)n_in; (void)out_size;
    const float* x     = (const float*)d_in[0];
    const float* g1    = (const float*)d_in[1];
    const float* b1    = (const float*)d_in[2];
    const float* Wqkv1 = (const float*)d_in[3];
    const float* bqkv1 = (const float*)d_in[4];
    const float* Wout1 = (const float*)d_in[5];
    const float* bout1 = (const float*)d_in[6];
    const float* g2    = (const float*)d_in[7];
    const float* b2    = (const float*)d_in[8];
    const float* Wqkv2 = (const float*)d_in[9];
    const float* bqkv2 = (const float*)d_in[10];
    const float* Wout2 = (const float*)d_in[11];
    const float* bout2 = (const float*)d_in[12];
    const float* gf    = (const float*)d_in[13];
    const float* bf    = (const float*)d_in[14];
    const float* Wf1   = (const float*)d_in[15];
    const float* bf1   = (const float*)d_in[16];
    const float* Wf2   = (const float*)d_in[17];
    const float* bf2   = (const float*)d_in[18];
    float* out = (float*)d_out;

    cudaFuncSetAttribute(ctx_kernel,  cudaFuncAttributeMaxDynamicSharedMemorySize, CC*64*4);
    cudaFuncSetAttribute(attn_kernel, cudaFuncAttributeMaxDynamicSharedMemorySize, 2*CC*STR*4);
    cudaFuncSetAttribute(ffn_kernel,  cudaFuncAttributeMaxDynamicSharedMemorySize, (CC+FF)*STR*4);

    fold_kernel<<<2305, 256>>>(Wqkv1, bqkv1, g1, b1, Wqkv2, bqkv2, g2, b2,
                               Wf1, bf1, gf, bf, Wout1, Wout2, Wf2);
    qstats_kernel<<<BB*16, 256>>>(x);
    softmax_np_kernel<<<BB*PP + BB*64, 256>>>();
    xs_kernel<<<BB*CC, 256>>>(x);
    ctx_kernel<<<BB*5, 256, CC*64*4>>>();
    attn_kernel<<<BB*256, 512, 2*CC*STR*4>>>(x, bout1, bout2);
    ffn_kernel<<<BB*256, 512, (CC+FF)*STR*4>>>(out, bf2);
}